// round 4
// baseline (speedup 1.0000x reference)
#include <cuda_runtime.h>

#define N_NODES 500000
#define N_EDGES 4000000
#define EPT 8  // edges per thread in edge kernels

// ---- scratch (device globals; no allocation allowed) ----
__device__ int    g_cnt[N_NODES];
__device__ float4 g_y[N_NODES];      // {dinv*x0, dinv*x1, dinv*x2, dinv}
__device__ float4 g_agg1[N_NODES];   // accumulated neighbor sums (xyz used, w junk)
__device__ float  g_s[N_NODES];      // dinv * (relu(h1) @ W2)
__device__ float  g_agg2[N_NODES];

// ---- K1: degree count over edge targets, 8 edges/thread ----
__global__ void __launch_bounds__(256) k_count(const int* __restrict__ col) {
    int i = blockIdx.x * blockDim.x + threadIdx.x;
    if (i < N_EDGES / EPT) {
        int4 c0 = reinterpret_cast<const int4*>(col)[2 * i + 0];
        int4 c1 = reinterpret_cast<const int4*>(col)[2 * i + 1];
        atomicAdd(&g_cnt[c0.x], 1);
        atomicAdd(&g_cnt[c0.y], 1);
        atomicAdd(&g_cnt[c0.z], 1);
        atomicAdd(&g_cnt[c0.w], 1);
        atomicAdd(&g_cnt[c1.x], 1);
        atomicAdd(&g_cnt[c1.y], 1);
        atomicAdd(&g_cnt[c1.z], 1);
        atomicAdd(&g_cnt[c1.w], 1);
    }
}

// ---- K2: dinv = rsqrt(deg), y = dinv*x, agg1 init = self-loop term ----
__global__ void __launch_bounds__(256) k_prep(const float* __restrict__ x) {
    int v = blockIdx.x * blockDim.x + threadIdx.x;
    if (v < N_NODES) {
        float d = rsqrtf((float)(g_cnt[v] + 1));  // +1 self-loop
        float x0 = x[3 * v + 0];
        float x1 = x[3 * v + 1];
        float x2 = x[3 * v + 2];
        float4 y = make_float4(d * x0, d * x1, d * x2, d);
        g_y[v]    = y;  // gather source (w carries dinv)
        g_agg1[v] = y;  // self-loop term pre-seeded
    }
}

// ---- K3: edge scatter, layer 1: float4 atomic per edge, 8 edges/thread ----
__global__ void __launch_bounds__(256) k_scatter1(const int* __restrict__ row,
                                                  const int* __restrict__ col) {
    int i = blockIdx.x * blockDim.x + threadIdx.x;
    if (i < N_EDGES / EPT) {
        int4 r0 = reinterpret_cast<const int4*>(row)[2 * i + 0];
        int4 r1 = reinterpret_cast<const int4*>(row)[2 * i + 1];
        int4 c0 = reinterpret_cast<const int4*>(col)[2 * i + 0];
        int4 c1 = reinterpret_cast<const int4*>(col)[2 * i + 1];
        // 8 independent gathers in flight
        float4 y0 = g_y[r0.x];
        float4 y1 = g_y[r0.y];
        float4 y2 = g_y[r0.z];
        float4 y3 = g_y[r0.w];
        float4 y4 = g_y[r1.x];
        float4 y5 = g_y[r1.y];
        float4 y6 = g_y[r1.z];
        float4 y7 = g_y[r1.w];
        atomicAdd(&g_agg1[c0.x], y0);
        atomicAdd(&g_agg1[c0.y], y1);
        atomicAdd(&g_agg1[c0.z], y2);
        atomicAdd(&g_agg1[c0.w], y3);
        atomicAdd(&g_agg1[c1.x], y4);
        atomicAdd(&g_agg1[c1.y], y5);
        atomicAdd(&g_agg1[c1.z], y6);
        atomicAdd(&g_agg1[c1.w], y7);
    }
}

// ---- K4: fused node MLP: h1 = relu((dinv*agg1) @ W1 + b1); s = dinv*(h1 @ W2) ----
__global__ void __launch_bounds__(256) k_mlp(const float* __restrict__ W1,
                                             const float* __restrict__ b1,
                                             const float* __restrict__ W2) {
    __shared__ float sW1[48];  // [3][16] row-major
    __shared__ float sb1[16];
    __shared__ float sW2[16];
    int t = threadIdx.x;
    if (t < 48) sW1[t] = W1[t];
    if (t < 16) { sb1[t] = b1[t]; sW2[t] = W2[t]; }
    __syncthreads();

    int v = blockIdx.x * blockDim.x + t;
    if (v < N_NODES) {
        float4 a = g_agg1[v];
        float  d = g_y[v].w;
        float t0 = d * a.x, t1 = d * a.y, t2 = d * a.z;
        float acc = 0.0f;
#pragma unroll
        for (int j = 0; j < 16; j++) {
            float h = fmaf(t0, sW1[j],
                      fmaf(t1, sW1[16 + j],
                      fmaf(t2, sW1[32 + j], sb1[j])));
            acc = fmaf(fmaxf(h, 0.0f), sW2[j], acc);
        }
        float s = d * acc;
        g_s[v]    = s;  // gather source for layer 2
        g_agg2[v] = s;  // self-loop term included
    }
}

// ---- K5: edge scatter, layer 2 (scalar), 8 edges/thread ----
__global__ void __launch_bounds__(256) k_scatter2(const int* __restrict__ row,
                                                  const int* __restrict__ col) {
    int i = blockIdx.x * blockDim.x + threadIdx.x;
    if (i < N_EDGES / EPT) {
        int4 r0 = reinterpret_cast<const int4*>(row)[2 * i + 0];
        int4 r1 = reinterpret_cast<const int4*>(row)[2 * i + 1];
        int4 c0 = reinterpret_cast<const int4*>(col)[2 * i + 0];
        int4 c1 = reinterpret_cast<const int4*>(col)[2 * i + 1];
        float s0 = g_s[r0.x];
        float s1 = g_s[r0.y];
        float s2 = g_s[r0.z];
        float s3 = g_s[r0.w];
        float s4 = g_s[r1.x];
        float s5 = g_s[r1.y];
        float s6 = g_s[r1.z];
        float s7 = g_s[r1.w];
        atomicAdd(&g_agg2[c0.x], s0);
        atomicAdd(&g_agg2[c0.y], s1);
        atomicAdd(&g_agg2[c0.z], s2);
        atomicAdd(&g_agg2[c0.w], s3);
        atomicAdd(&g_agg2[c1.x], s4);
        atomicAdd(&g_agg2[c1.y], s5);
        atomicAdd(&g_agg2[c1.z], s6);
        atomicAdd(&g_agg2[c1.w], s7);
    }
}

// ---- K6: finalize: out = dinv*agg2 + b2 ----
__global__ void __launch_bounds__(256) k_final(float* __restrict__ out,
                                               const float* __restrict__ b2) {
    int v = blockIdx.x * blockDim.x + threadIdx.x;
    if (v < N_NODES) {
        out[v] = fmaf(g_y[v].w, g_agg2[v], b2[0]);
    }
}

extern "C" void kernel_launch(void* const* d_in, const int* in_sizes, int n_in,
                              void* d_out, int out_size) {
    const float* x   = (const float*)d_in[0];
    const int*   ei  = (const int*)d_in[1];   // [2][E]: row = ei, col = ei + E
    const float* W1  = (const float*)d_in[2]; // [3][16]
    const float* b1  = (const float*)d_in[3]; // [16]
    const float* W2  = (const float*)d_in[4]; // [16][1]
    const float* b2  = (const float*)d_in[5]; // [1]
    float* out = (float*)d_out;

    const int* row = ei;
    const int* col = ei + N_EDGES;

    const int T = 256;
    const int nb_nodes = (N_NODES + T - 1) / T;
    const int nb_e8    = (N_EDGES / EPT + T - 1) / T;

    int* cnt_ptr = nullptr;
    cudaGetSymbolAddress((void**)&cnt_ptr, g_cnt);
    cudaMemsetAsync(cnt_ptr, 0, N_NODES * sizeof(int));

    k_count<<<nb_e8, T>>>(col);
    k_prep<<<nb_nodes, T>>>(x);
    k_scatter1<<<nb_e8, T>>>(row, col);
    k_mlp<<<nb_nodes, T>>>(W1, b1, W2);
    k_scatter2<<<nb_e8, T>>>(row, col);
    k_final<<<nb_nodes, T>>>(out, b2);
}